// round 8
// baseline (speedup 1.0000x reference)
#include <cuda_runtime.h>
#include <cuda_bf16.h>
#include <cstdint>
#include <cstddef>

typedef unsigned long long ull;

#define T_   2048
#define B_   128
#define IN_  128
#define H_   256
#define G4_  1024
#define OUT_ 64

#define BG_  16   // batch groups (= clusters)
#define HCN_ 8    // hidden-slice CTAs per cluster
#define BC_  8    // batches per group

#define WPAD 132  // padded row stride (floats) for fp32 GEMM smem tiles

// ---- k_rec smem layout (bytes) ----
// B2 tile: [8 b][132 kp][{hi2,lo2} u32 pair] = 8448 B per parity (kp = 0..127)
#define SM_B2SZ   8448
#define SM_B2(p)  ((p) * SM_B2SZ)
#define SM_MBAR   (2 * SM_B2SZ)
#define REC_SMEM  (SM_MBAR + 64)

#define OUT_SMEM ((64 * 256 + 32 * WPAD) * 4)

// tx bytes per consumer mbarrier per step: 8 CTAs x 128 pair-threads x 8 B
#define TX_BYTES 8192

// ---------------- device scratch ----------------
__device__ float d_xg[(size_t)T_ * B_ * G4_];    // [t][bg][hc][bb][col]
__device__ float d_rbuf[(size_t)T_ * B_ * H_];   // [t][b][h]

// ---------------- f32x2 helpers ----------------
__device__ __forceinline__ ull pack2(float x) {
    unsigned xi = __float_as_uint(x);
    ull r;
    asm("mov.b64 %0, {%1, %1};" : "=l"(r) : "r"(xi));
    return r;
}
__device__ __forceinline__ ull ffma2(ull a, ull b, ull c) {
    ull d;
    asm("fma.rn.f32x2 %0, %1, %2, %3;" : "=l"(d) : "l"(a), "l"(b), "l"(c));
    return d;
}
__device__ __forceinline__ void unpack2(ull v, float& lo, float& hi) {
    unsigned l, h;
    asm("mov.b64 {%0, %1}, %2;" : "=r"(l), "=r"(h) : "l"(v));
    lo = __uint_as_float(l);
    hi = __uint_as_float(h);
}

// fast branch-free activations (MUFU-based, ~1e-6 rel err)
__device__ __forceinline__ float rcpa(float x) {
    float r;
    asm("rcp.approx.f32 %0, %1;" : "=f"(r) : "f"(x));
    return r;
}
__device__ __forceinline__ float sigf(float x) { return rcpa(1.0f + __expf(-x)); }
__device__ __forceinline__ float tanhfa(float x) { return 1.0f - 2.0f * rcpa(1.0f + __expf(2.0f * x)); }

// bf16 mma m16n8k16 row.col, f32 accum
__device__ __forceinline__ void mma16816(float* d,
                                         uint32_t a0, uint32_t a1, uint32_t a2, uint32_t a3,
                                         uint32_t b0, uint32_t b1) {
    asm volatile(
        "mma.sync.aligned.m16n8k16.row.col.f32.bf16.bf16.f32 "
        "{%0,%1,%2,%3}, {%4,%5,%6,%7}, {%8,%9}, {%0,%1,%2,%3};"
        : "+f"(d[0]), "+f"(d[1]), "+f"(d[2]), "+f"(d[3])
        : "r"(a0), "r"(a1), "r"(a2), "r"(a3), "r"(b0), "r"(b1));
}

// pack two fp32 into bf16 hi-word + residual lo-word
__device__ __forceinline__ void split2(float a, float b, uint32_t& hi, uint32_t& lo) {
    __nv_bfloat16 ha = __float2bfloat16(a), hb = __float2bfloat16(b);
    hi = (uint32_t)__bfloat16_as_ushort(ha) | ((uint32_t)__bfloat16_as_ushort(hb) << 16);
    __nv_bfloat16 la = __float2bfloat16(a - __bfloat162float(ha));
    __nv_bfloat16 lb = __float2bfloat16(b - __bfloat162float(hb));
    lo = (uint32_t)__bfloat16_as_ushort(la) | ((uint32_t)__bfloat16_as_ushort(lb) << 16);
}

// ---------------- cluster / mbarrier helpers ----------------
__device__ __forceinline__ uint32_t smem_u32(const void* p) {
    uint32_t a;
    asm("{ .reg .u64 t; cvta.to.shared.u64 t, %1; cvt.u32.u64 %0, t; }" : "=r"(a) : "l"(p));
    return a;
}
__device__ __forceinline__ uint32_t mapa_u32(uint32_t addr, uint32_t rank) {
    uint32_t r;
    asm("mapa.shared::cluster.u32 %0, %1, %2;" : "=r"(r) : "r"(addr), "r"(rank));
    return r;
}
__device__ __forceinline__ void st_async64(uint32_t daddr, ull val, uint32_t dmbar) {
    asm volatile(
        "st.async.weak.shared::cluster.mbarrier::complete_tx::bytes.b64 [%0], %1, [%2];"
        :: "r"(daddr), "l"(val), "r"(dmbar) : "memory");
}
#define MBAR_INIT(a, c) asm volatile("mbarrier.init.shared.b64 [%0], %1;" :: "r"(a), "r"(c) : "memory")
#define MBAR_EXPECT(a, tx) asm volatile( \
    "mbarrier.arrive.expect_tx.shared.b64 _, [%0], %1;" :: "r"(a), "r"(tx) : "memory")
#define MBAR_WAIT_CL(a, par) do { \
    asm volatile("{\n\t.reg .pred P;\nWAITC_%=:\n\t" \
                 "mbarrier.try_wait.parity.acquire.cluster.shared::cta.b64 P, [%0], %1;\n\t" \
                 "@!P bra WAITC_%=;\n\t}" :: "r"(a), "r"(par) : "memory"); \
} while (0)
#define CLUSTER_SYNC() do { \
    asm volatile("barrier.cluster.arrive.aligned;" ::: "memory"); \
    asm volatile("barrier.cluster.wait.aligned;" ::: "memory"); \
} while (0)

// ---------------- kernel 1: xg = x @ W_ih^T + b_ih + b_hh (permuted) -------
__global__ __launch_bounds__(256, 2) void k_xg(const float* __restrict__ x,
                                               const float* __restrict__ W_ih,
                                               const float* __restrict__ b_ih,
                                               const float* __restrict__ b_hh) {
    __shared__ float xs[32 * WPAD];
    __shared__ float ws[32 * WPAD];
    const int hc = blockIdx.x;
    const int t = blockIdx.y;
    const int u = threadIdx.x;
    const int tm = u & 15;
    const int tn = u >> 4;

    ull acc[8][4];
#pragma unroll
    for (int j = 0; j < 8; j++)
#pragma unroll
        for (int p = 0; p < 4; p++) acc[j][p] = 0ull;

    const int bs = u >> 1, half = u & 1;
    const int colS = u >> 1;
    const int RS = (colS & 3) * H_ + hc * 32 + (colS >> 2);
    const float* xsrc = x + ((size_t)t * B_ + bs) * IN_ + half * 16;
    const float* wsrc = W_ih + (size_t)RS * IN_ + half * 16;

    for (int kc = 0; kc < IN_; kc += 32) {
#pragma unroll
        for (int q = 0; q < 4; q++) {
            float4 v = *(const float4*)(xsrc + kc + q * 4);
            int kl = half * 16 + q * 4;
            xs[(kl + 0) * WPAD + bs] = v.x;
            xs[(kl + 1) * WPAD + bs] = v.y;
            xs[(kl + 2) * WPAD + bs] = v.z;
            xs[(kl + 3) * WPAD + bs] = v.w;
            float4 w = *(const float4*)(wsrc + kc + q * 4);
            ws[(kl + 0) * WPAD + colS] = w.x;
            ws[(kl + 1) * WPAD + colS] = w.y;
            ws[(kl + 2) * WPAD + colS] = w.z;
            ws[(kl + 3) * WPAD + colS] = w.w;
        }
        __syncthreads();
#pragma unroll 8
        for (int kk = 0; kk < 32; kk++) {
            const float* xr = &xs[kk * WPAD + tm * 8];
            ulonglong2 xa = *(const ulonglong2*)xr;
            ulonglong2 xb = *(const ulonglong2*)(xr + 4);
            ull xp0 = xa.x, xp1 = xa.y, xp2 = xb.x, xp3 = xb.y;
            const float* wr = &ws[kk * WPAD + tn * 8];
            float4 wa = *(const float4*)wr;
            float4 wb = *(const float4*)(wr + 4);
            float wv[8] = {wa.x, wa.y, wa.z, wa.w, wb.x, wb.y, wb.z, wb.w};
#pragma unroll
            for (int j = 0; j < 8; j++) {
                ull wj = pack2(wv[j]);
                acc[j][0] = ffma2(wj, xp0, acc[j][0]);
                acc[j][1] = ffma2(wj, xp1, acc[j][1]);
                acc[j][2] = ffma2(wj, xp2, acc[j][2]);
                acc[j][3] = ffma2(wj, xp3, acc[j][3]);
            }
        }
        __syncthreads();
    }
    size_t base = (((size_t)t * BG_ + tm) * HCN_ + hc) * 1024;
#pragma unroll
    for (int j = 0; j < 8; j++) {
        int col = tn * 8 + j;
        int R = (col & 3) * H_ + hc * 32 + (col >> 2);
        float bv = b_ih[R] + b_hh[R];
#pragma unroll
        for (int p = 0; p < 4; p++) {
            float lo, hi;
            unpack2(acc[j][p], lo, hi);
            d_xg[base + (size_t)(2 * p) * 128 + col] = lo + bv;
            d_xg[base + (size_t)(2 * p + 1) * 128 + col] = hi + bv;
        }
    }
}

// ---------------- kernel 2: persistent recurrence ----------------
// 16 clusters of 8 CTAs, 256 threads (8 warps). Each warp: 16 gate-rows, FULL
// K=256 (48 MMAs, W frags in 128 regs). No __syncthreads in the t-loop; gate
// transpose via in-warp shfl; each thread owns one (hidden,b) cell end-to-end.
__global__ __cluster_dims__(HCN_, 1, 1) __launch_bounds__(256, 1)
void k_rec(const float* __restrict__ W_hh) {
    extern __shared__ char smem[];
    const uint32_t sb = smem_u32(smem);

    const int u = threadIdx.x;
    const int wid = u >> 5;
    const int lane = u & 31;
    const int g = lane >> 2, tg = lane & 3;
    const int bg = blockIdx.x >> 3;
    const int hc = blockIdx.x & 7;

    // --- mbarriers: init + pre-arm both parities ---
    if (u == 0) {
        MBAR_INIT(sb + SM_MBAR + 0, 1);
        MBAR_INIT(sb + SM_MBAR + 8, 1);
        MBAR_EXPECT(sb + SM_MBAR + 0, TX_BYTES);  // first completes for t=2
        MBAR_EXPECT(sb + SM_MBAR + 8, TX_BYTES);  // first completes for t=1
    }
    // zero parity-0 B tile (h0 = 0)
    for (int i = u; i < SM_B2SZ / 4; i += 256)
        ((uint32_t*)(smem + SM_B2(0)))[i] = 0;

    // --- hoisted DSMEM base addresses ---
    uint32_t rbase[HCN_];
#pragma unroll
    for (int r = 0; r < HCN_; r++) rbase[r] = mapa_u32(sb, (uint32_t)r);

    // --- W fragments -> registers, full K=256 per warp ---
    const int R0 = wid * 16;
    uint32_t ahi[16][4], alo[16][4];
#pragma unroll
    for (int kt = 0; kt < 16; kt++) {
#pragma unroll
        for (int p = 0; p < 4; p++) {
            int row = R0 + g + (p & 1) * 8;
            int kk = kt * 16 + tg * 2 + (p >> 1) * 8;
            int gate = row & 3, hu = row >> 2;
            const float* wp = W_hh + (size_t)(gate * H_ + hc * 32 + hu) * H_ + kk;
            float2 v = *(const float2*)wp;
            split2(v.x, v.y, ahi[kt][p], alo[kt][p]);
        }
    }
    __syncthreads();
    CLUSTER_SYNC();   // mbarriers + zeroed tiles visible cluster-wide

    // epilogue identity: one (hidden, batch) cell per thread
    const int hu_l = lane >> 3;          // 0..3 local hidden unit
    const int b = lane & 7;              // batch within group
    const int hh = wid * 4 + hu_l;       // 0..31 hidden within CTA slice
    float c = 0.0f;
    const size_t xgbase = ((size_t)bg * HCN_ + hc) * 1024 + (size_t)b * 128 + (size_t)hh * 4;
    const int src_base = (hu_l & 1) * 4; // transpose source-g base
    const int src_tg = b >> 1;
    const bool low_half = (hu_l < 2);
    const bool odd_b = (b & 1);
    const uint32_t kpg = (uint32_t)((hc * 32 + hh) >> 1);  // B-tile pair index (even hh)

    for (int t = 0; t < T_; t++) {
        const int par = t & 1;

        // --- xg prefetch (DRAM latency hides under wait + GEMM) ---
        float4 xg4 = *(const float4*)&d_xg[(size_t)t * (BG_ * HCN_ * 1024) + xgbase];

        // --- wait for all 8 peers' h (tx-counted mbarrier), re-arm for t+2 ---
        if (t > 0) {
            uint32_t amb = sb + SM_MBAR + par * 8;
            uint32_t ph = (uint32_t)(((t - 1) >> 1) & 1);
            MBAR_WAIT_CL(amb, ph);
            if (u == 0) MBAR_EXPECT(amb, TX_BYTES);
        }

        // --- GEMM: 16 kt full-K; 3 independent accumulator chains ---
        const char* b2B = smem + SM_B2(par);
        float dA[4] = {0.f, 0.f, 0.f, 0.f};
        float dB4[4] = {0.f, 0.f, 0.f, 0.f};
        float dC[4] = {0.f, 0.f, 0.f, 0.f};
#pragma unroll
        for (int kt = 0; kt < 16; kt++) {
            int kp0 = kt * 8;
            ull w0 = *(const ull*)(b2B + ((size_t)g * 132 + kp0 + tg) * 8);
            ull w1 = *(const ull*)(b2B + ((size_t)g * 132 + kp0 + tg + 4) * 8);
            uint32_t bh0 = (uint32_t)w0, bl0 = (uint32_t)(w0 >> 32);
            uint32_t bh1 = (uint32_t)w1, bl1 = (uint32_t)(w1 >> 32);
            mma16816(dA, ahi[kt][0], ahi[kt][1], ahi[kt][2], ahi[kt][3], bh0, bh1);
            mma16816(dB4, ahi[kt][0], ahi[kt][1], ahi[kt][2], ahi[kt][3], bl0, bl1);
            mma16816(dC, alo[kt][0], alo[kt][1], alo[kt][2], alo[kt][3], bh0, bh1);
        }
        float d0 = dA[0] + dB4[0] + dC[0];
        float d1 = dA[1] + dB4[1] + dC[1];
        float d2 = dA[2] + dB4[2] + dC[2];
        float d3 = dA[3] + dB4[3] + dC[3];

        // --- in-warp transpose: gather 4 gates for this (hu_l, b) via shfl ---
        float gate[4];
#pragma unroll
        for (int gi = 0; gi < 4; gi++) {
            int src = (src_base + gi) * 4 + src_tg;
            float v0 = __shfl_sync(0xFFFFFFFFu, d0, src);
            float v1 = __shfl_sync(0xFFFFFFFFu, d1, src);
            float v2 = __shfl_sync(0xFFFFFFFFu, d2, src);
            float v3 = __shfl_sync(0xFFFFFFFFu, d3, src);
            float ve = low_half ? v0 : v2;
            float vo = low_half ? v1 : v3;
            gate[gi] = odd_b ? vo : ve;
        }

        // --- activations + state update ---
        float si = gate[0] + xg4.x;
        float sf = gate[1] + xg4.y;
        float sg = gate[2] + xg4.z;
        float so = gate[3] + xg4.w;
        float iv = sigf(si);
        float fv = sigf(sf);
        float gv = tanhfa(sg);
        float ov = sigf(so);
        c = fv * c + iv * gv;
        float hval = ov * tanhfa(c);

        // --- publish h (bf16 hi/lo, adjacent-hh pair packed) to all 8 peers ---
        __nv_bfloat16 bh = __float2bfloat16(hval);
        __nv_bfloat16 bl = __float2bfloat16(hval - __bfloat162float(bh));
        unsigned hiw = (unsigned)__bfloat16_as_ushort(bh);
        unsigned low = (unsigned)__bfloat16_as_ushort(bl);
        unsigned hin = __shfl_down_sync(0xFFFFFFFFu, hiw, 8);   // partner: hu_l+1
        unsigned lon = __shfl_down_sync(0xFFFFFFFFu, low, 8);
        if (((hu_l & 1) == 0) && t < T_ - 1) {
            ull v = (ull)(hiw | (hin << 16)) | ((ull)(low | (lon << 16)) << 32);
            const int parw = (t + 1) & 1;
            uint32_t offD = (uint32_t)SM_B2(parw) + ((uint32_t)b * 132 + kpg) * 8;
            uint32_t offM = (uint32_t)SM_MBAR + (uint32_t)parw * 8;
#pragma unroll
            for (int r = 0; r < HCN_; r++) {
                st_async64(rbase[r] + offD, v, rbase[r] + offM);
            }
        }
        // off-critical-path DRAM store
        d_rbuf[((size_t)t * B_ + bg * BC_ + b) * H_ + hc * 32 + hh] = hval;
    }
    CLUSTER_SYNC();
}

// ---------------- kernel 3: out = r_out @ W_out^T + b_out ----------------
__global__ __launch_bounds__(256, 2) void k_out(const float* __restrict__ W_out,
                                                const float* __restrict__ b_out,
                                                float* __restrict__ out) {
    extern __shared__ float sm[];
    float* wo = sm;
    float* rs = sm + 64 * 256;
    const int t = blockIdx.x;
    const int u = threadIdx.x;

    for (int i = u; i < 64 * 256 / 4; i += 256)
        *(float4*)&wo[i * 4] = *(const float4*)&W_out[i * 4];

    const int bq = u & 15, oq = u >> 4;
    ull acc[4][4];
#pragma unroll
    for (int j = 0; j < 4; j++)
#pragma unroll
        for (int p = 0; p < 4; p++) acc[j][p] = 0ull;

    const int bs = u >> 1, half = u & 1;
    const float* rsrc = d_rbuf + ((size_t)t * B_ + bs) * H_ + half * 16;
    __syncthreads();

    for (int kc = 0; kc < H_; kc += 32) {
#pragma unroll
        for (int q = 0; q < 4; q++) {
            float4 v = *(const float4*)(rsrc + kc + q * 4);
            int kl = half * 16 + q * 4;
            rs[(kl + 0) * WPAD + bs] = v.x;
            rs[(kl + 1) * WPAD + bs] = v.y;
            rs[(kl + 2) * WPAD + bs] = v.z;
            rs[(kl + 3) * WPAD + bs] = v.w;
        }
        __syncthreads();
#pragma unroll 4
        for (int kk = 0; kk < 32; kk++) {
            int k = kc + kk;
            const float* xr = &rs[kk * WPAD + bq * 8];
            ulonglong2 xa = *(const ulonglong2*)xr;
            ulonglong2 xb = *(const ulonglong2*)(xr + 4);
            ull xp0 = xa.x, xp1 = xa.y, xp2 = xb.x, xp3 = xb.y;
#pragma unroll
            for (int j = 0; j < 4; j++) {
                ull wj = pack2(wo[(oq * 4 + j) * 256 + k]);
                acc[j][0] = ffma2(wj, xp0, acc[j][0]);
                acc[j][1] = ffma2(wj, xp1, acc[j][1]);
                acc[j][2] = ffma2(wj, xp2, acc[j][2]);
                acc[j][3] = ffma2(wj, xp3, acc[j][3]);
            }
        }
        __syncthreads();
    }
#pragma unroll
    for (int j = 0; j < 4; j++) {
        int o = oq * 4 + j;
        float bv = b_out[o];
#pragma unroll
        for (int p = 0; p < 4; p++) {
            float lo, hi;
            unpack2(acc[j][p], lo, hi);
            int b0 = bq * 8 + 2 * p;
            out[((size_t)t * B_ + b0) * OUT_ + o] = lo + bv;
            out[((size_t)t * B_ + b0 + 1) * OUT_ + o] = hi + bv;
        }
    }
}

// ---------------- launcher ----------------
extern "C" void kernel_launch(void* const* d_in, const int* in_sizes, int n_in,
                              void* d_out, int out_size) {
    const float* x     = (const float*)d_in[0];
    const float* W_ih  = (const float*)d_in[1];
    const float* W_hh  = (const float*)d_in[2];
    const float* b_ih  = (const float*)d_in[3];
    const float* b_hh  = (const float*)d_in[4];
    const float* W_out = (const float*)d_in[5];
    const float* b_out = (const float*)d_in[6];
    float* out = (float*)d_out;

    cudaFuncSetAttribute(k_rec, cudaFuncAttributeMaxDynamicSharedMemorySize, REC_SMEM);
    cudaFuncSetAttribute(k_out, cudaFuncAttributeMaxDynamicSharedMemorySize, OUT_SMEM);

    k_xg<<<dim3(HCN_, T_), 256>>>(x, W_ih, b_ih, b_hh);
    k_rec<<<BG_ * HCN_, 256, REC_SMEM>>>(W_hh);
    k_out<<<T_, 256, OUT_SMEM>>>(W_out, b_out, out);
}